// round 2
// baseline (speedup 1.0000x reference)
#include <cuda_runtime.h>
#include <cuda_bf16.h>
#include <math.h>

// Shapes (fixed per reference): B=512, T=256, F=D=1024
#define BB 512
#define TT 256
#define FF 1024

// Scratch (allocation-free rule: __device__ globals)
__device__ float g_q[BB * FF];
__device__ float g_u[BB * FF];
__device__ float g_c[BB * FF];

// ---------------------------------------------------------------------------
// Tiled fp32 GEMM: Y[M,N] = X[M,K] * op(W) (+ bias)
//   TRANSB=true : op(W)[k,n] = W[n,k]   (Y = X @ W^T), W is [N,K]
//   TRANSB=false: op(W)[k,n] = W[k,n]   (Y = X @ W),   W is [K,N]
// 64x64 block tile, BK=16, 256 threads, 4x4 per thread.
// ---------------------------------------------------------------------------
template <bool TRANSB, bool HASBIAS>
__global__ __launch_bounds__(256)
void gemm64(const float* __restrict__ X, const float* __restrict__ W,
            const float* __restrict__ bias, float* __restrict__ Y,
            int M, int N, int K)
{
    __shared__ float As[64][16];
    __shared__ float Bs[16][68];   // padded to dodge STS conflicts in NT path

    const int tid = threadIdx.x;
    const int tx = tid & 15;       // n sub-tile
    const int ty = tid >> 4;       // m sub-tile
    const int m0 = blockIdx.y * 64;
    const int n0 = blockIdx.x * 64;

    float acc[4][4];
#pragma unroll
    for (int i = 0; i < 4; i++)
#pragma unroll
        for (int j = 0; j < 4; j++) acc[i][j] = 0.f;

    for (int kt = 0; kt < K; kt += 16) {
        // Load A tile: 64x16 floats = 256 float4, one per thread
        {
            int r  = tid >> 2;
            int c4 = (tid & 3) * 4;
            float4 v = *reinterpret_cast<const float4*>(X + (size_t)(m0 + r) * K + kt + c4);
            *reinterpret_cast<float4*>(&As[r][c4]) = v;
        }
        // Load B tile
        if (TRANSB) {
            // W is [N,K]; read row (n0+r), cols kt..kt+15; store transposed
            int r  = tid >> 2;          // n within tile
            int c4 = (tid & 3) * 4;     // k within tile
            float4 v = *reinterpret_cast<const float4*>(W + (size_t)(n0 + r) * K + kt + c4);
            Bs[c4 + 0][r] = v.x;
            Bs[c4 + 1][r] = v.y;
            Bs[c4 + 2][r] = v.z;
            Bs[c4 + 3][r] = v.w;
        } else {
            // W is [K,N]; read row (kt+r), cols n0..n0+63
            int r  = tid >> 4;          // k within tile
            int c4 = (tid & 15) * 4;    // n within tile
            float4 v = *reinterpret_cast<const float4*>(W + (size_t)(kt + r) * N + n0 + c4);
            *reinterpret_cast<float4*>(&Bs[r][c4]) = v;
        }
        __syncthreads();

#pragma unroll
        for (int k = 0; k < 16; k++) {
            float a0 = As[ty * 4 + 0][k];
            float a1 = As[ty * 4 + 1][k];
            float a2 = As[ty * 4 + 2][k];
            float a3 = As[ty * 4 + 3][k];
            float4 b = *reinterpret_cast<float4*>(&Bs[k][tx * 4]);
            acc[0][0] += a0 * b.x; acc[0][1] += a0 * b.y; acc[0][2] += a0 * b.z; acc[0][3] += a0 * b.w;
            acc[1][0] += a1 * b.x; acc[1][1] += a1 * b.y; acc[1][2] += a1 * b.z; acc[1][3] += a1 * b.w;
            acc[2][0] += a2 * b.x; acc[2][1] += a2 * b.y; acc[2][2] += a2 * b.z; acc[2][3] += a2 * b.w;
            acc[3][0] += a3 * b.x; acc[3][1] += a3 * b.y; acc[3][2] += a3 * b.z; acc[3][3] += a3 * b.w;
        }
        __syncthreads();
    }

    float4 bv = make_float4(0.f, 0.f, 0.f, 0.f);
    if (HASBIAS) bv = *reinterpret_cast<const float4*>(bias + n0 + tx * 4);

#pragma unroll
    for (int i = 0; i < 4; i++) {
        float4 o;
        o.x = acc[i][0] + bv.x;
        o.y = acc[i][1] + bv.y;
        o.z = acc[i][2] + bv.z;
        o.w = acc[i][3] + bv.w;
        *reinterpret_cast<float4*>(Y + (size_t)(m0 + ty * 4 + i) * N + n0 + tx * 4) = o;
    }
}

// ---------------------------------------------------------------------------
// Fused single-query attention with online softmax, single pass over p.
//   scores[b,t] = u[b] . p[b,t]  ;  c[b] = softmax_t(scores) . p[b]
// One block per b. 256 threads. Tile of 8 t-rows (32KB) staged in smem.
// Each thread owns 4 features of the running accumulator (registers).
// ---------------------------------------------------------------------------
__global__ __launch_bounds__(256)
void attn_kernel(const float* __restrict__ u, const float* __restrict__ p,
                 float* __restrict__ c)
{
    __shared__ float4 u_s[FF / 4];           // 4 KB
    __shared__ float4 tile[8 * (FF / 4)];    // 32 KB: 8 t-rows x 1024 f
    __shared__ float  s_sm[8];

    const int b    = blockIdx.x;
    const int tid  = threadIdx.x;
    const int lane = tid & 31;
    const int w    = tid >> 5;               // 8 warps; warp w scores local row w

    u_s[tid] = reinterpret_cast<const float4*>(u + (size_t)b * FF)[tid];

    const float4* pb = reinterpret_cast<const float4*>(p + (size_t)b * TT * FF);

    float4 acc = make_float4(0.f, 0.f, 0.f, 0.f);
    float m = -INFINITY;
    float l = 0.f;

    for (int it = 0; it < TT / 8; it++) {
        __syncthreads();  // previous iter's tile readers done (also orders u_s on it=0)

        // Stage 8x1024 floats: 2048 float4, 8 per thread (coalesced, MLP=8)
        const float4* src = pb + it * 8 * (FF / 4);
#pragma unroll
        for (int j = 0; j < 8; j++) tile[j * 256 + tid] = src[j * 256 + tid];
        __syncthreads();

        // Scores: warp w computes dot(u, tile row w) over 1024 elems
        float partial = 0.f;
#pragma unroll
        for (int k = 0; k < 8; k++) {
            float4 a  = tile[w * 256 + k * 32 + lane];
            float4 uu = u_s[k * 32 + lane];
            partial += a.x * uu.x + a.y * uu.y + a.z * uu.z + a.w * uu.w;
        }
#pragma unroll
        for (int off = 16; off; off >>= 1)
            partial += __shfl_xor_sync(0xffffffffu, partial, off);
        if (lane == 0) s_sm[w] = partial;
        __syncthreads();

        // Online softmax update (computed redundantly per thread — all identical)
        float s0[8], wv[8];
        float tmax = -INFINITY;
#pragma unroll
        for (int i = 0; i < 8; i++) { s0[i] = s_sm[i]; tmax = fmaxf(tmax, s0[i]); }
        float m_new = fmaxf(m, tmax);
        float cf = __expf(m - m_new);        // first iter: exp(-inf)=0, acc is 0 anyway
        float wsum = 0.f;
#pragma unroll
        for (int i = 0; i < 8; i++) { wv[i] = __expf(s0[i] - m_new); wsum += wv[i]; }
        l = l * cf + wsum;
        m = m_new;
        acc.x *= cf; acc.y *= cf; acc.z *= cf; acc.w *= cf;

        // Accumulate weighted rows; thread owns features [tid*4, tid*4+4)
#pragma unroll
        for (int i = 0; i < 8; i++) {
            float4 v = tile[i * 256 + tid];
            acc.x += wv[i] * v.x;
            acc.y += wv[i] * v.y;
            acc.z += wv[i] * v.z;
            acc.w += wv[i] * v.w;
        }
    }

    float inv = 1.f / l;
    float4 outv = make_float4(acc.x * inv, acc.y * inv, acc.z * inv, acc.w * inv);
    reinterpret_cast<float4*>(c + (size_t)b * FF)[tid] = outv;
}

// ---------------------------------------------------------------------------
// kernel_launch
// Inputs: 0=z_state[512,1024] 1=past_predictions[512,256,1024]
//         2=Wq[1024,1024] 3=Wk[1024,1024] 4=Wv[1024,1024]
//         5=bq[1024] 6=bk[1024] 7=bv[1024]
// Output: context [512,1024] fp32
// ---------------------------------------------------------------------------
extern "C" void kernel_launch(void* const* d_in, const int* in_sizes, int n_in,
                              void* d_out, int out_size)
{
    const float* z    = (const float*)d_in[0];
    const float* past = (const float*)d_in[1];
    const float* Wq   = (const float*)d_in[2];
    const float* Wk   = (const float*)d_in[3];
    const float* Wv   = (const float*)d_in[4];
    const float* bq   = (const float*)d_in[5];
    // bk (d_in[6]) is softmax-invariant (constant per-b score shift) — unused.
    const float* bv   = (const float*)d_in[7];
    float* out = (float*)d_out;

    void *qp, *up, *cp;
    cudaGetSymbolAddress(&qp, g_q);
    cudaGetSymbolAddress(&up, g_u);
    cudaGetSymbolAddress(&cp, g_c);
    float* q_buf = (float*)qp;
    float* u_buf = (float*)up;
    float* c_buf = (float*)cp;

    dim3 gg(FF / 64, BB / 64);   // (16, 8)

    // q = z @ Wq^T + bq
    gemm64<true, true><<<gg, 256>>>(z, Wq, bq, q_buf, BB, FF, FF);
    // u = q @ Wk
    gemm64<false, false><<<gg, 256>>>(q_buf, Wk, nullptr, u_buf, BB, FF, FF);
    // c[b] = softmax_t(u[b].p[b,t]) . p[b]
    attn_kernel<<<BB, 256>>>(u_buf, past, c_buf);
    // out = c @ Wv^T + bv
    gemm64<true, true><<<gg, 256>>>(c_buf, Wv, bv, out, BB, FF, FF);
}

// round 3
// speedup vs baseline: 1.2792x; 1.2792x over previous
#include <cuda_runtime.h>
#include <cuda_bf16.h>
#include <math.h>

// Shapes (fixed per reference): B=512, T=256, F=D=1024
#define BB 512
#define TT 256
#define FF 1024

// Scratch (allocation-free rule: __device__ globals)
__device__ float g_q[BB * FF];
__device__ float g_u[BB * FF];
__device__ float g_c[BB * FF];

// ---------------- packed f32x2 helpers (SASS FFMA2 — ptxas won't auto-fuse) ---
__device__ __forceinline__ void ffma2(unsigned long long& d,
                                      unsigned long long a,
                                      unsigned long long b) {
    asm("fma.rn.f32x2 %0, %1, %2, %0;" : "+l"(d) : "l"(a), "l"(b));
}
__device__ __forceinline__ unsigned long long dup2(float x) {
    unsigned long long r;
    asm("mov.b64 %0, {%1, %1};" : "=l"(r) : "f"(x));
    return r;
}
__device__ __forceinline__ unsigned long long pack2(float x, float y) {
    unsigned long long r;
    asm("mov.b64 %0, {%1, %2};" : "=l"(r) : "f"(x), "f"(y));
    return r;
}
__device__ __forceinline__ float2 unpack2(unsigned long long v) {
    float2 f;
    asm("mov.b64 {%0, %1}, %2;" : "=f"(f.x), "=f"(f.y) : "l"(v));
    return f;
}

// ---------------------------------------------------------------------------
// Tiled fp32 GEMM using packed FFMA2: Y[M,N] = X[M,K] * op(W) (+ bias)
//   TRANSB=true : op(W) = W^T (W is [N,K]);  false: op(W) = W (W is [K,N])
// 64x64 tile, BK=16, 256 threads, 4x4 per thread, double-buffered smem.
// smem stored K-major: As[k][m], Bs[k][n]  -> 2x LDS.128 per k-step.
// ---------------------------------------------------------------------------
#define LDA 68   // padded row (floats); 272B, 16B-aligned
template <bool TRANSB, bool HASBIAS>
__global__ __launch_bounds__(256)
void gemm64(const float* __restrict__ X, const float* __restrict__ W,
            const float* __restrict__ bias, float* __restrict__ Y,
            int M, int N, int K)
{
    __shared__ float As[2][16][LDA];
    __shared__ float Bs[2][16][LDA];

    const int tid = threadIdx.x;
    const int tx = tid & 15;       // n sub-tile
    const int ty = tid >> 4;       // m sub-tile
    const int m0 = blockIdx.y * 64;
    const int n0 = blockIdx.x * 64;

    // global load coordinates
    const int ar  = tid >> 2;          // row within 64 (A and NT-B)
    const int ac4 = (tid & 3) * 4;     // k offset within 16
    const int bk  = tid >> 4;          // k row (NN-B)
    const int bn4 = (tid & 15) * 4;    // n offset (NN-B)

    const float* Aptr = X + (size_t)(m0 + ar) * K + ac4;
    const float* Bptr = TRANSB ? (W + (size_t)(n0 + ar) * K + ac4)
                               : (W + (size_t)bk * N + n0 + bn4);

    unsigned long long acc[4][2];
#pragma unroll
    for (int i = 0; i < 4; i++) { acc[i][0] = 0ull; acc[i][1] = 0ull; }

    // ---- prologue: stage 0
    {
        float4 va = *reinterpret_cast<const float4*>(Aptr);
        As[0][ac4 + 0][ar] = va.x;
        As[0][ac4 + 1][ar] = va.y;
        As[0][ac4 + 2][ar] = va.z;
        As[0][ac4 + 3][ar] = va.w;
        if (TRANSB) {
            float4 vb = *reinterpret_cast<const float4*>(Bptr);
            Bs[0][ac4 + 0][ar] = vb.x;
            Bs[0][ac4 + 1][ar] = vb.y;
            Bs[0][ac4 + 2][ar] = vb.z;
            Bs[0][ac4 + 3][ar] = vb.w;
        } else {
            float4 vb = *reinterpret_cast<const float4*>(Bptr);
            *reinterpret_cast<float4*>(&Bs[0][bk][bn4]) = vb;
        }
    }
    __syncthreads();

    int s = 0;
    for (int kt = 16;; kt += 16) {
        float4 va, vb;
        const bool more = (kt < K);
        if (more) {
            va = *reinterpret_cast<const float4*>(Aptr + kt);
            vb = *reinterpret_cast<const float4*>(Bptr + (TRANSB ? kt : (size_t)kt * N));
        }

        // ---- compute current stage
#pragma unroll
        for (int k = 0; k < 16; k++) {
            float4 a = *reinterpret_cast<float4*>(&As[s][k][ty * 4]);
            float4 b = *reinterpret_cast<float4*>(&Bs[s][k][tx * 4]);
            unsigned long long b01 = pack2(b.x, b.y);
            unsigned long long b23 = pack2(b.z, b.w);
            unsigned long long a0 = dup2(a.x), a1 = dup2(a.y);
            unsigned long long a2 = dup2(a.z), a3 = dup2(a.w);
            ffma2(acc[0][0], a0, b01); ffma2(acc[0][1], a0, b23);
            ffma2(acc[1][0], a1, b01); ffma2(acc[1][1], a1, b23);
            ffma2(acc[2][0], a2, b01); ffma2(acc[2][1], a2, b23);
            ffma2(acc[3][0], a3, b01); ffma2(acc[3][1], a3, b23);
        }
        if (!more) break;

        // ---- store next stage (s^1 is free: its last readers finished before
        // the syncthreads that admitted us into this iteration)
        const int ns = s ^ 1;
        As[ns][ac4 + 0][ar] = va.x;
        As[ns][ac4 + 1][ar] = va.y;
        As[ns][ac4 + 2][ar] = va.z;
        As[ns][ac4 + 3][ar] = va.w;
        if (TRANSB) {
            Bs[ns][ac4 + 0][ar] = vb.x;
            Bs[ns][ac4 + 1][ar] = vb.y;
            Bs[ns][ac4 + 2][ar] = vb.z;
            Bs[ns][ac4 + 3][ar] = vb.w;
        } else {
            *reinterpret_cast<float4*>(&Bs[ns][bk][bn4]) = vb;
        }
        __syncthreads();
        s = ns;
    }

    float4 bv = make_float4(0.f, 0.f, 0.f, 0.f);
    if (HASBIAS) bv = *reinterpret_cast<const float4*>(bias + n0 + tx * 4);

#pragma unroll
    for (int i = 0; i < 4; i++) {
        float2 v0 = unpack2(acc[i][0]);
        float2 v1 = unpack2(acc[i][1]);
        float4 o;
        o.x = v0.x + bv.x;
        o.y = v0.y + bv.y;
        o.z = v1.x + bv.z;
        o.w = v1.y + bv.w;
        *reinterpret_cast<float4*>(Y + (size_t)(m0 + ty * 4 + i) * N + n0 + tx * 4) = o;
    }
}

// ---------------------------------------------------------------------------
// Fused single-query attention, online softmax, single HBM pass over p,
// 2-stage cp.async pipeline (8 t-rows = 32KB per stage).
//   scores[b,t] = u[b].p[b,t] ;  c[b] = softmax_t(scores) . p[b]
// One block per b, 256 threads, 8 warps (warp w scores local row w).
// ---------------------------------------------------------------------------
#define TILE_F4 (8 * (FF / 4))   // 2048 float4 per stage

__device__ __forceinline__ void cp_async16(void* smem_dst, const void* gsrc) {
    unsigned saddr = (unsigned)__cvta_generic_to_shared(smem_dst);
    asm volatile("cp.async.cg.shared.global [%0], [%1], 16;"
                 :: "r"(saddr), "l"(gsrc));
}
__device__ __forceinline__ void cp_commit() {
    asm volatile("cp.async.commit_group;");
}
template <int N>
__device__ __forceinline__ void cp_wait() {
    asm volatile("cp.async.wait_group %0;" :: "n"(N));
}

__global__ __launch_bounds__(256)
void attn_kernel(const float* __restrict__ u, const float* __restrict__ p,
                 float* __restrict__ c)
{
    extern __shared__ float4 smem[];
    float4* u_s   = smem;               // 256 float4 (4KB)
    float4* tiles = smem + 256;         // 2 stages x 2048 float4 (64KB)
    float*  s_sm  = (float*)(smem + 256 + 2 * TILE_F4);  // 8 floats

    const int b    = blockIdx.x;
    const int tid  = threadIdx.x;
    const int lane = tid & 31;
    const int w    = tid >> 5;

    u_s[tid] = reinterpret_cast<const float4*>(u + (size_t)b * FF)[tid];

    const float4* pb = reinterpret_cast<const float4*>(p + (size_t)b * TT * FF);

    // prologue: tile 0 -> stage 0
#pragma unroll
    for (int j = 0; j < 8; j++)
        cp_async16(&tiles[j * 256 + tid], &pb[j * 256 + tid]);
    cp_commit();

    float4 acc = make_float4(0.f, 0.f, 0.f, 0.f);
    float m = -INFINITY;
    float l = 0.f;

    for (int it = 0; it < TT / 8; it++) {
        const int s = it & 1;
        if (it + 1 < TT / 8) {
            const float4* src = pb + (it + 1) * TILE_F4;
            float4* dst = tiles + (s ^ 1) * TILE_F4;
#pragma unroll
            for (int j = 0; j < 8; j++)
                cp_async16(&dst[j * 256 + tid], &src[j * 256 + tid]);
            cp_commit();
            cp_wait<1>();
        } else {
            cp_wait<0>();
        }
        __syncthreads();

        const float4* tile = tiles + s * TILE_F4;

        // scores: warp w computes dot(u, row w)
        float partial = 0.f;
#pragma unroll
        for (int k = 0; k < 8; k++) {
            float4 a  = tile[w * 256 + k * 32 + lane];
            float4 uu = u_s[k * 32 + lane];
            partial += a.x * uu.x + a.y * uu.y + a.z * uu.z + a.w * uu.w;
        }
#pragma unroll
        for (int off = 16; off; off >>= 1)
            partial += __shfl_xor_sync(0xffffffffu, partial, off);
        if (lane == 0) s_sm[w] = partial;
        __syncthreads();

        // online softmax update (redundant per thread, identical values)
        float s0[8], wv[8];
        float tmax = -INFINITY;
#pragma unroll
        for (int i = 0; i < 8; i++) { s0[i] = s_sm[i]; tmax = fmaxf(tmax, s0[i]); }
        float m_new = fmaxf(m, tmax);
        float cf = __expf(m - m_new);   // it=0: exp(-inf)=0, acc is 0 anyway
        float wsum = 0.f;
#pragma unroll
        for (int i = 0; i < 8; i++) { wv[i] = __expf(s0[i] - m_new); wsum += wv[i]; }
        l = l * cf + wsum;
        m = m_new;
        acc.x *= cf; acc.y *= cf; acc.z *= cf; acc.w *= cf;

        // accumulate weighted rows; thread owns features [tid*4, tid*4+4)
#pragma unroll
        for (int i = 0; i < 8; i++) {
            float4 v = tile[i * 256 + tid];
            acc.x += wv[i] * v.x;
            acc.y += wv[i] * v.y;
            acc.z += wv[i] * v.z;
            acc.w += wv[i] * v.w;
        }
        __syncthreads();   // stage s free for the cp.async issued at it+2
    }

    float inv = 1.f / l;
    reinterpret_cast<float4*>(c + (size_t)b * FF)[tid] =
        make_float4(acc.x * inv, acc.y * inv, acc.z * inv, acc.w * inv);
}

// ---------------------------------------------------------------------------
// kernel_launch
// Inputs: 0=z_state[512,1024] 1=past_predictions[512,256,1024]
//         2=Wq[1024,1024] 3=Wk[1024,1024] 4=Wv[1024,1024]
//         5=bq[1024] 6=bk[1024] 7=bv[1024]
// Output: context [512,1024] fp32
// ---------------------------------------------------------------------------
extern "C" void kernel_launch(void* const* d_in, const int* in_sizes, int n_in,
                              void* d_out, int out_size)
{
    const float* z    = (const float*)d_in[0];
    const float* past = (const float*)d_in[1];
    const float* Wq   = (const float*)d_in[2];
    const float* Wk   = (const float*)d_in[3];
    const float* Wv   = (const float*)d_in[4];
    const float* bq   = (const float*)d_in[5];
    // bk (d_in[6]) is softmax-invariant (constant per-b score shift) — unused.
    const float* bv   = (const float*)d_in[7];
    float* out = (float*)d_out;

    void *qp, *up, *cp;
    cudaGetSymbolAddress(&qp, g_q);
    cudaGetSymbolAddress(&up, g_u);
    cudaGetSymbolAddress(&cp, g_c);
    float* q_buf = (float*)qp;
    float* u_buf = (float*)up;
    float* c_buf = (float*)cp;

    const int attn_smem = (256 + 2 * TILE_F4) * sizeof(float4) + 32 * sizeof(float);
    static int configured = 0;
    if (!configured) {
        cudaFuncSetAttribute(attn_kernel,
                             cudaFuncAttributeMaxDynamicSharedMemorySize, attn_smem);
        configured = 1;
    }

    dim3 gg(FF / 64, BB / 64);   // (16, 8)

    // q = z @ Wq^T + bq
    gemm64<true, true><<<gg, 256>>>(z, Wq, bq, q_buf, BB, FF, FF);
    // u = q @ Wk
    gemm64<false, false><<<gg, 256>>>(q_buf, Wk, nullptr, u_buf, BB, FF, FF);
    // c[b] = softmax_t(u[b].p[b,t]) . p[b]
    attn_kernel<<<BB, 256, attn_smem>>>(u_buf, past, c_buf);
    // out = c @ Wv^T + bv
    gemm64<true, true><<<gg, 256>>>(c_buf, Wv, bv, out, BB, FF, FF);
}